// round 3
// baseline (speedup 1.0000x reference)
#include <cuda_runtime.h>
#include <cuda_fp16.h>

#define NN 500000
#define EE 2000000
#define GG 64
#define EPS 1e-5f

// ---------------- scratch (device globals; no allocs allowed) ----------------
__device__ __align__(16) int    g_deg[NN];
__device__ __align__(16) float  g_dis[NN];
__device__ __align__(16) int    g_c[NN];
__device__ __align__(16) float  g_S[NN * 9];
__device__ __align__(16) __half g_z1[(size_t)NN * 64];   // relu(affine(S@M1)) in fp16
__device__ __align__(16) float  g_agg2[(size_t)NN * 64]; // seeded with self-loop term
__device__ __align__(16) float  g_M1[9 * 64];
__device__ __align__(16) float  g_a1[64];
__device__ __align__(16) float  g_sh1[64];
__device__ __align__(16) float  g_mom[64];               // [0..8]=sum S, [9..53]=upper-tri of S S^T
__device__ __align__(16) float  g_s2[64];
__device__ __align__(16) float  g_q2[64];
__device__ __align__(16) float  g_psum[GG * 64];
__device__ __align__(16) int    g_pmax[GG * 64];
__device__ __align__(16) int    g_pmin[GG * 64];
__device__                int    g_cnt[GG];

// ---------------- helpers ----------------
__device__ __forceinline__ void red_add_v4(float* p, float4 v) {
    asm volatile("red.global.add.v4.f32 [%0], {%1, %2, %3, %4};"
                 :: "l"(p), "f"(v.x), "f"(v.y), "f"(v.z), "f"(v.w) : "memory");
}
__device__ __forceinline__ void atomicMaxFloat(int* addr, float v) {
    if (v >= 0.0f) atomicMax(addr, __float_as_int(v));
    else           atomicMin((unsigned int*)addr, __float_as_uint(v));
}
__device__ __forceinline__ void atomicMinFloat(int* addr, float v) {
    if (v >= 0.0f) atomicMin(addr, __float_as_int(v));
    else           atomicMax((unsigned int*)addr, __float_as_uint(v));
}

// ---------------- small init ----------------
__global__ void k_small_init() {
    int i = blockIdx.x * blockDim.x + threadIdx.x;
    if (i < GG * 64) {
        g_pmax[i] = 0xFF800000;
        g_pmin[i] = 0x7F800000;
        g_psum[i] = 0.0f;
    }
    if (i < 64) {
        g_mom[i] = 0.0f;
        g_s2[i] = 0.0f; g_q2[i] = 0.0f;
    }
}

// ---------------- per-graph node counts: binary search over sorted batch -----
__global__ void k_cnt(const int* __restrict__ batch) {
    int g = threadIdx.x;
    if (g >= GG) return;
    int lo0 = 0, hi0 = NN;
    while (lo0 < hi0) { int m = (lo0 + hi0) >> 1; if (batch[m] < g) lo0 = m + 1; else hi0 = m; }
    int lo1 = lo0, hi1 = NN;
    while (lo1 < hi1) { int m = (lo1 + hi1) >> 1; if (batch[m] < g + 1) lo1 = m + 1; else hi1 = m; }
    g_cnt[g] = lo1 - lo0;
}

// ---------------- M1 = [emb_type || emb_inv] @ W1  (9 x 64) ----------------
__global__ void k_prep(const float* __restrict__ emb_type,
                       const float* __restrict__ emb_inv,
                       const float* __restrict__ W1) {
    int t = threadIdx.x;
    if (t >= 9 * 64) return;
    int combo = t >> 6;
    int f = t & 63;
    int ty = combo / 3, iv = combo % 3;
    float acc = 0.0f;
#pragma unroll
    for (int k = 0; k < 16; k++) {
        acc = fmaf(emb_type[ty * 16 + k], W1[k * 64 + f], acc);
        acc = fmaf(emb_inv[iv * 16 + k], W1[(16 + k) * 64 + f], acc);
    }
    g_M1[combo * 64 + f] = acc;
}

// ---------------- degree histogram ----------------
__global__ void k_deg(const int* __restrict__ edst) {
    int e = blockIdx.x * blockDim.x + threadIdx.x;
    if (e < EE) atomicAdd(&g_deg[edst[e]], 1);
}

// ---------------- per-node: dis, combo idx, self-loop seed of S ----------------
__global__ void k_dis(const int* __restrict__ node_type,
                      const int* __restrict__ num_inv) {
    int v = blockIdx.x * blockDim.x + threadIdx.x;
    if (v >= NN) return;
    int d = g_deg[v] + 1;
    float dis = rsqrtf((float)d);
    g_dis[v] = dis;
    int c = node_type[v] * 3 + num_inv[v];
    g_c[v] = c;
    g_S[v * 9 + c] = dis * dis;
}

// ---------------- layer-1 bucket aggregation: 1 atomic per edge ----------------
__global__ void k_edge1(const int* __restrict__ esrc, const int* __restrict__ edst) {
    int e = blockIdx.x * blockDim.x + threadIdx.x;
    if (e >= EE) return;
    int s = esrc[e], d = edst[e];
    atomicAdd(&g_S[d * 9 + g_c[s]], g_dis[s] * g_dis[d]);
}

// ---------------- S moments: sum S (9) + upper-tri of sum S S^T (45) ----------
__global__ __launch_bounds__(256) void k_stats() {
    __shared__ float sS[256 * 9];
    __shared__ float sred[8][54];
    float m[54];
#pragma unroll
    for (int i = 0; i < 54; i++) m[i] = 0.0f;

    int tiles = (NN + 255) / 256;
    for (int t = blockIdx.x; t < tiles; t += gridDim.x) {
        int base = t * 256;
        int cnt = min(256, NN - base);
        int tot = cnt * 9;
        __syncthreads();
        for (int i = threadIdx.x; i < tot; i += 256) sS[i] = g_S[(size_t)base * 9 + i];
        __syncthreads();
        if ((int)threadIdx.x < cnt) {
            float r[9];
#pragma unroll
            for (int j = 0; j < 9; j++) r[j] = sS[threadIdx.x * 9 + j];
            int k = 9;
#pragma unroll
            for (int i = 0; i < 9; i++) {
                m[i] += r[i];
#pragma unroll
                for (int j = i; j < 9; j++) m[k++] = fmaf(r[i], r[j], m[k]);
            }
        }
    }
    // warp reduce all 54
#pragma unroll
    for (int v = 0; v < 54; v++) {
#pragma unroll
        for (int o = 16; o > 0; o >>= 1) m[v] += __shfl_down_sync(0xffffffffu, m[v], o);
    }
    int lane = threadIdx.x & 31, warp = threadIdx.x >> 5;
    if (lane == 0) {
#pragma unroll
        for (int v = 0; v < 54; v++) sred[warp][v] = m[v];
    }
    __syncthreads();
    if (threadIdx.x < 54) {
        float acc = 0.0f;
#pragma unroll
        for (int w = 0; w < 8; w++) acc += sred[w][threadIdx.x];
        atomicAdd(&g_mom[threadIdx.x], acc);
    }
}

// ---------------- BN1 affine params from moments ----------------
__global__ void k_bn1(const float* __restrict__ gamma1, const float* __restrict__ beta1) {
    int f = threadIdx.x;
    if (f >= 64) return;
    float mcol[9];
#pragma unroll
    for (int t = 0; t < 9; t++) mcol[t] = g_M1[t * 64 + f];
    float mean = 0.0f;
#pragma unroll
    for (int t = 0; t < 9; t++) mean = fmaf(g_mom[t], mcol[t], mean);
    mean /= (float)NN;
    float e2 = 0.0f;
    int k = 9;
#pragma unroll
    for (int i = 0; i < 9; i++) {
#pragma unroll
        for (int j = i; j < 9; j++) {
            float term = g_mom[k++] * mcol[i] * mcol[j];
            e2 += (i == j) ? term : 2.0f * term;
        }
    }
    e2 /= (float)NN;
    float var = e2 - mean * mean;
    float a = rsqrtf(var + EPS) * gamma1[f];
    g_a1[f] = a;
    g_sh1[f] = beta1[f] - mean * a;
}

// -------- layer-1b: z1 = relu(affine(S@M1)) fp16 + seed agg2 with self term ----
__global__ __launch_bounds__(256) void k_layer1b() {
    __shared__ float sM1[9 * 64];
    for (int i = threadIdx.x; i < 9 * 64; i += 256) sM1[i] = g_M1[i];
    __syncthreads();

    int lane = threadIdx.x & 31;
    int warp = (blockIdx.x * blockDim.x + threadIdx.x) >> 5;
    int nwarps = (gridDim.x * blockDim.x) >> 5;

    float2 av = ((const float2*)g_a1)[lane];
    float2 shv = ((const float2*)g_sh1)[lane];

    for (int v = warp; v < NN; v += nwarps) {
        float y0 = 0.f, y1 = 0.f;
#pragma unroll
        for (int t = 0; t < 9; t++) {
            float sv = g_S[(size_t)v * 9 + t];   // warp-broadcast load
            y0 = fmaf(sv, sM1[t * 64 + 2 * lane], y0);
            y1 = fmaf(sv, sM1[t * 64 + 2 * lane + 1], y1);
        }
        float z0 = fmaxf(fmaf(y0, av.x, shv.x), 0.f);
        float z1 = fmaxf(fmaf(y1, av.y, shv.y), 0.f);
        ((half2*)g_z1)[(size_t)v * 32 + lane] = __floats2half2_rn(z0, z1);
        float dd = g_dis[v];
        float id = dd * dd;
        ((float2*)g_agg2)[(size_t)v * 32 + lane] = make_float2(id * z0, id * z1);
    }
}

// ---------- layer-2 edge phase: fp16 gather (L2-resident), fp32 vector red ----
__global__ __launch_bounds__(256) void k_edge2(const int* __restrict__ esrc,
                                               const int* __restrict__ edst) {
    int lane = threadIdx.x & 31;
    int sub = lane & 7;                    // 16B chunk of the 128B fp16 row
    int eo = lane >> 3;                    // 4 edges per warp
    int gw = (blockIdx.x * blockDim.x + threadIdx.x) >> 5;
    int nw = (gridDim.x * blockDim.x) >> 5;

    for (int e = gw * 4 + eo; e < EE; e += nw * 4) {
        int s = esrc[e], d = edst[e];
        float norm = g_dis[s] * g_dis[d];
        uint4 raw = ((const uint4*)(g_z1 + (size_t)s * 64))[sub];
        float2 f0 = __half22float2(*(half2*)&raw.x);
        float2 f1 = __half22float2(*(half2*)&raw.y);
        float2 f2 = __half22float2(*(half2*)&raw.z);
        float2 f3 = __half22float2(*(half2*)&raw.w);
        float* dst = g_agg2 + (size_t)d * 64 + sub * 8;
        red_add_v4(dst,     make_float4(f0.x * norm, f0.y * norm, f1.x * norm, f1.y * norm));
        red_add_v4(dst + 4, make_float4(f2.x * norm, f2.y * norm, f3.x * norm, f3.y * norm));
    }
}

// ---------- layer-2 GEMM + BN2 stats + fused graph pooling ----------
#define TN 128
#define NB2 512
__global__ __launch_bounds__(256, 2) void k_layer2pool(const int* __restrict__ batch,
                                                       const float* __restrict__ W2) {
    __shared__ float4 As4[TN * 16];   // 32 KB
    __shared__ float4 Bs4[64 * 16];   // 16 KB
    int tid = threadIdx.x;
    int tf = tid & 15;
    int tn = tid >> 4;

    for (int i = tid; i < 1024; i += 256) Bs4[i] = ((const float4*)W2)[i];

    float psum[4] = {0, 0, 0, 0};
    float pmx[4], pmn[4];
#pragma unroll
    for (int j = 0; j < 4; j++) { pmx[j] = -__int_as_float(0x7F800000); pmn[j] = __int_as_float(0x7F800000); }
    int gcur = -1;
    float ss[4] = {0, 0, 0, 0}, sq[4] = {0, 0, 0, 0};

    int tiles = (NN + TN - 1) / TN;
    int tpb = (tiles + NB2 - 1) / NB2;
    int t0 = blockIdx.x * tpb;
    int t1 = min(t0 + tpb, tiles);

    for (int t = t0; t < t1; t++) {
        int base = t * TN;
        __syncthreads();
#pragma unroll
        for (int kb = 0; kb < 8; kb++) {
            int nl = tn + 16 * kb;
            int v = base + nl;
            float4 val = {0.f, 0.f, 0.f, 0.f};
            if (v < NN) val = ((const float4*)g_agg2)[(size_t)v * 16 + tf];
            As4[nl * 16 + tf] = val;
        }
        __syncthreads();

        float4 acc[8];
#pragma unroll
        for (int i = 0; i < 8; i++) acc[i] = make_float4(0.f, 0.f, 0.f, 0.f);
#pragma unroll 4
        for (int kk = 0; kk < 16; kk++) {
            float4 b0 = Bs4[(4 * kk + 0) * 16 + tf];
            float4 b1 = Bs4[(4 * kk + 1) * 16 + tf];
            float4 b2 = Bs4[(4 * kk + 2) * 16 + tf];
            float4 b3 = Bs4[(4 * kk + 3) * 16 + tf];
#pragma unroll
            for (int i = 0; i < 8; i++) {
                float4 a = As4[(tn * 8 + i) * 16 + kk];
                acc[i].x = fmaf(a.x, b0.x, fmaf(a.y, b1.x, fmaf(a.z, b2.x, fmaf(a.w, b3.x, acc[i].x))));
                acc[i].y = fmaf(a.x, b0.y, fmaf(a.y, b1.y, fmaf(a.z, b2.y, fmaf(a.w, b3.y, acc[i].y))));
                acc[i].z = fmaf(a.x, b0.z, fmaf(a.y, b1.z, fmaf(a.z, b2.z, fmaf(a.w, b3.z, acc[i].z))));
                acc[i].w = fmaf(a.x, b0.w, fmaf(a.y, b1.w, fmaf(a.z, b2.w, fmaf(a.w, b3.w, acc[i].w))));
            }
        }

#pragma unroll
        for (int i = 0; i < 8; i++) {
            int v = base + tn * 8 + i;
            if (v >= NN) break;
            int g = batch[v];
            if (g != gcur) {
                if (gcur >= 0) {
                    int pb = gcur * 64 + tf * 4;
#pragma unroll
                    for (int j = 0; j < 4; j++) {
                        atomicAdd(&g_psum[pb + j], psum[j]);
                        atomicMaxFloat(&g_pmax[pb + j], pmx[j]);
                        atomicMinFloat(&g_pmin[pb + j], pmn[j]);
                    }
                }
                gcur = g;
#pragma unroll
                for (int j = 0; j < 4; j++) {
                    psum[j] = 0.f;
                    pmx[j] = -__int_as_float(0x7F800000);
                    pmn[j] = __int_as_float(0x7F800000);
                }
            }
            float y[4] = {acc[i].x, acc[i].y, acc[i].z, acc[i].w};
#pragma unroll
            for (int j = 0; j < 4; j++) {
                psum[j] += y[j];
                pmx[j] = fmaxf(pmx[j], y[j]);
                pmn[j] = fminf(pmn[j], y[j]);
                ss[j] += y[j];
                sq[j] = fmaf(y[j], y[j], sq[j]);
            }
        }
    }
    if (gcur >= 0) {
        int pb = gcur * 64 + tf * 4;
#pragma unroll
        for (int j = 0; j < 4; j++) {
            atomicAdd(&g_psum[pb + j], psum[j]);
            atomicMaxFloat(&g_pmax[pb + j], pmx[j]);
            atomicMinFloat(&g_pmin[pb + j], pmn[j]);
        }
    }
#pragma unroll
    for (int j = 0; j < 4; j++) {
        atomicAdd(&g_s2[tf * 4 + j], ss[j]);
        atomicAdd(&g_q2[tf * 4 + j], sq[j]);
    }
}

// ---------------- finalize ----------------
__global__ void k_final(const float* __restrict__ gamma2, const float* __restrict__ beta2,
                        float* __restrict__ out) {
    int f = threadIdx.x;
    if (f >= 64) return;
    float mu = g_s2[f] / (float)NN;
    float var = g_q2[f] / (float)NN - mu * mu;
    float a = rsqrtf(var + EPS) * gamma2[f];
    float sh = beta2[f] - mu * a;
    for (int g = 0; g < GG; g++) {
        float mx = __int_as_float(g_pmax[g * 64 + f]);
        float mn = __int_as_float(g_pmin[g * 64 + f]);
        float chosen = (a >= 0.f) ? mx : mn;
        out[g * 128 + f] = fmaf(chosen, a, sh);
        float c = fmaxf((float)g_cnt[g], 1.f);
        out[g * 128 + 64 + f] = fmaf(g_psum[g * 64 + f] / c, a, sh);
    }
}

// ---------------- launch ----------------
extern "C" void kernel_launch(void* const* d_in, const int* in_sizes, int n_in,
                              void* d_out, int out_size) {
    const int* node_type = (const int*)d_in[0];
    const int* num_inv   = (const int*)d_in[1];
    const int* edge      = (const int*)d_in[2];
    const int* batch     = (const int*)d_in[3];
    const float* emb_type = (const float*)d_in[4];
    const float* emb_inv  = (const float*)d_in[5];
    const float* W1       = (const float*)d_in[6];
    const float* W2       = (const float*)d_in[8];
    const float* gamma1   = (const float*)d_in[10];
    const float* beta1    = (const float*)d_in[11];
    const float* gamma2   = (const float*)d_in[12];
    const float* beta2    = (const float*)d_in[13];
    float* out = (float*)d_out;

    const int* esrc = edge;
    const int* edst = edge + EE;

    void *pDeg, *pS;
    cudaGetSymbolAddress(&pDeg, g_deg);
    cudaGetSymbolAddress(&pS, g_S);
    cudaMemsetAsync(pDeg, 0, (size_t)NN * sizeof(int));
    cudaMemsetAsync(pS, 0, (size_t)NN * 9 * sizeof(float));

    k_small_init<<<(GG * 64 + 255) / 256, 256>>>();
    k_cnt<<<1, 64>>>(batch);
    k_prep<<<1, 576>>>(emb_type, emb_inv, W1);
    k_deg<<<(EE + 255) / 256, 256>>>(edst);
    k_dis<<<(NN + 255) / 256, 256>>>(node_type, num_inv);
    k_edge1<<<(EE + 255) / 256, 256>>>(esrc, edst);
    k_stats<<<296, 256>>>();
    k_bn1<<<1, 64>>>(gamma1, beta1);
    k_layer1b<<<1184, 256>>>();
    k_edge2<<<1184, 256>>>(esrc, edst);
    k_layer2pool<<<NB2, 256>>>(batch, W2);
    k_final<<<1, 64>>>(gamma2, beta2, out);
}

// round 4
// speedup vs baseline: 1.2885x; 1.2885x over previous
#include <cuda_runtime.h>
#include <cuda_fp16.h>

#define NN 500000
#define EE 2000000
#define GG 64
#define EPS 1e-5f
#define SCAN_B 512
#define NBS ((NN + SCAN_B - 1) / SCAN_B)   // 977

// ---------------- scratch (device globals; no allocs allowed) ----------------
__device__ __align__(16) int    g_deg[NN];
__device__ __align__(16) float  g_dis[NN];
__device__ __align__(16) int    g_c[NN];
__device__ __align__(16) int    g_off[NN + 1];
__device__ __align__(16) int    g_cur[NN];
__device__ __align__(16) int    g_bsum[NBS];
__device__ __align__(16) int    g_bpre[NBS];
__device__ __align__(16) int    g_srcs[EE];
__device__ __align__(16) float  g_S[NN * 9];
__device__ __align__(16) __half g_z1[(size_t)NN * 64];   // relu(affine(S@M1)) fp16
__device__ __align__(16) float  g_agg2[(size_t)NN * 64];
__device__ __align__(16) float  g_M1[9 * 64];
__device__ __align__(16) float  g_a1[64];
__device__ __align__(16) float  g_sh1[64];
__device__ __align__(16) float  g_mom[64];
__device__ __align__(16) float  g_s2[64];
__device__ __align__(16) float  g_q2[64];
__device__ __align__(16) float  g_psum[GG * 64];
__device__ __align__(16) int    g_pmax[GG * 64];
__device__ __align__(16) int    g_pmin[GG * 64];
__device__                int    g_cnt[GG];

// ---------------- helpers ----------------
__device__ __forceinline__ void atomicMaxFloat(int* addr, float v) {
    if (v >= 0.0f) atomicMax(addr, __float_as_int(v));
    else           atomicMin((unsigned int*)addr, __float_as_uint(v));
}
__device__ __forceinline__ void atomicMinFloat(int* addr, float v) {
    if (v >= 0.0f) atomicMin(addr, __float_as_int(v));
    else           atomicMax((unsigned int*)addr, __float_as_uint(v));
}

// ---------------- small init ----------------
__global__ void k_small_init() {
    int i = blockIdx.x * blockDim.x + threadIdx.x;
    if (i < GG * 64) {
        g_pmax[i] = 0xFF800000;
        g_pmin[i] = 0x7F800000;
        g_psum[i] = 0.0f;
    }
    if (i < 64) {
        g_mom[i] = 0.0f;
        g_s2[i] = 0.0f; g_q2[i] = 0.0f;
    }
}

// ---------------- per-graph node counts: binary search over sorted batch -----
__global__ void k_cnt(const int* __restrict__ batch) {
    int g = threadIdx.x;
    if (g >= GG) return;
    int lo0 = 0, hi0 = NN;
    while (lo0 < hi0) { int m = (lo0 + hi0) >> 1; if (batch[m] < g) lo0 = m + 1; else hi0 = m; }
    int lo1 = lo0, hi1 = NN;
    while (lo1 < hi1) { int m = (lo1 + hi1) >> 1; if (batch[m] < g + 1) lo1 = m + 1; else hi1 = m; }
    g_cnt[g] = lo1 - lo0;
}

// ---------------- M1 = [emb_type || emb_inv] @ W1  (9 x 64) ----------------
__global__ void k_prep(const float* __restrict__ emb_type,
                       const float* __restrict__ emb_inv,
                       const float* __restrict__ W1) {
    int t = threadIdx.x;
    if (t >= 9 * 64) return;
    int combo = t >> 6;
    int f = t & 63;
    int ty = combo / 3, iv = combo % 3;
    float acc = 0.0f;
#pragma unroll
    for (int k = 0; k < 16; k++) {
        acc = fmaf(emb_type[ty * 16 + k], W1[k * 64 + f], acc);
        acc = fmaf(emb_inv[iv * 16 + k], W1[(16 + k) * 64 + f], acc);
    }
    g_M1[combo * 64 + f] = acc;
}

// ---------------- degree histogram ----------------
__global__ void k_deg(const int* __restrict__ edst) {
    int e = blockIdx.x * blockDim.x + threadIdx.x;
    if (e < EE) atomicAdd(&g_deg[edst[e]], 1);
}

// ---------------- CSR scan (3 stages) ----------------
__global__ __launch_bounds__(SCAN_B) void k_scan1() {
    __shared__ int s[SCAN_B];
    int gid = blockIdx.x * SCAN_B + threadIdx.x;
    int v = (gid < NN) ? g_deg[gid] : 0;
    s[threadIdx.x] = v;
    __syncthreads();
    for (int o = 1; o < SCAN_B; o <<= 1) {
        int x = s[threadIdx.x];
        if (threadIdx.x >= o) x += s[threadIdx.x - o];
        __syncthreads();
        s[threadIdx.x] = x;
        __syncthreads();
    }
    if (threadIdx.x == SCAN_B - 1) g_bsum[blockIdx.x] = s[SCAN_B - 1];
}
__global__ __launch_bounds__(1024) void k_scan2() {
    __shared__ int s[1024];
    int t = threadIdx.x;
    int v = (t < NBS) ? g_bsum[t] : 0;
    s[t] = v;
    __syncthreads();
    for (int o = 1; o < 1024; o <<= 1) {
        int x = s[t];
        if (t >= o) x += s[t - o];
        __syncthreads();
        s[t] = x;
        __syncthreads();
    }
    if (t < NBS) g_bpre[t] = s[t] - v;   // exclusive
}
__global__ __launch_bounds__(SCAN_B) void k_scan3() {
    __shared__ int s[SCAN_B];
    int gid = blockIdx.x * SCAN_B + threadIdx.x;
    int v = (gid < NN) ? g_deg[gid] : 0;
    s[threadIdx.x] = v;
    __syncthreads();
    for (int o = 1; o < SCAN_B; o <<= 1) {
        int x = s[threadIdx.x];
        if (threadIdx.x >= o) x += s[threadIdx.x - o];
        __syncthreads();
        s[threadIdx.x] = x;
        __syncthreads();
    }
    if (gid < NN) {
        int excl = s[threadIdx.x] - v + g_bpre[blockIdx.x];
        g_off[gid] = excl;
        g_cur[gid] = excl;
        if (gid == NN - 1) g_off[NN] = excl + v;
    }
}

// ---------------- scatter edges into CSR ----------------
__global__ void k_scatter(const int* __restrict__ esrc, const int* __restrict__ edst) {
    int e = blockIdx.x * blockDim.x + threadIdx.x;
    if (e >= EE) return;
    int d = edst[e];
    int pos = atomicAdd(&g_cur[d], 1);
    g_srcs[pos] = esrc[e];
}

// ---------------- per-node: dis, combo idx, write full S row (incl zeros) -----
__global__ void k_dis(const int* __restrict__ node_type,
                      const int* __restrict__ num_inv) {
    int v = blockIdx.x * blockDim.x + threadIdx.x;
    if (v >= NN) return;
    int d = g_deg[v] + 1;
    float dis = rsqrtf((float)d);
    g_dis[v] = dis;
    int c = node_type[v] * 3 + num_inv[v];
    g_c[v] = c;
    float id = dis * dis;
#pragma unroll
    for (int t = 0; t < 9; t++) g_S[(size_t)v * 9 + t] = (t == c) ? id : 0.0f;
}

// ---------------- layer-1 bucket aggregation: 1 atomic per edge ----------------
__global__ void k_edge1(const int* __restrict__ esrc, const int* __restrict__ edst) {
    int e = blockIdx.x * blockDim.x + threadIdx.x;
    if (e >= EE) return;
    int s = esrc[e], d = edst[e];
    atomicAdd(&g_S[(size_t)d * 9 + g_c[s]], g_dis[s] * g_dis[d]);
}

// ---------------- S moments: sum S (9) + upper-tri of sum S S^T (45) ----------
__global__ __launch_bounds__(256) void k_stats() {
    __shared__ float sS[256 * 9];
    __shared__ float sred[8][54];
    float m[54];
#pragma unroll
    for (int i = 0; i < 54; i++) m[i] = 0.0f;

    int tiles = (NN + 255) / 256;
    for (int t = blockIdx.x; t < tiles; t += gridDim.x) {
        int base = t * 256;
        int cnt = min(256, NN - base);
        int tot = cnt * 9;
        __syncthreads();
        for (int i = threadIdx.x; i < tot; i += 256) sS[i] = g_S[(size_t)base * 9 + i];
        __syncthreads();
        if ((int)threadIdx.x < cnt) {
            float r[9];
#pragma unroll
            for (int j = 0; j < 9; j++) r[j] = sS[threadIdx.x * 9 + j];
            int k = 9;
#pragma unroll
            for (int i = 0; i < 9; i++) {
                m[i] += r[i];
#pragma unroll
                for (int j = i; j < 9; j++) { m[k] = fmaf(r[i], r[j], m[k]); k++; }
            }
        }
    }
#pragma unroll
    for (int v = 0; v < 54; v++) {
#pragma unroll
        for (int o = 16; o > 0; o >>= 1) m[v] += __shfl_down_sync(0xffffffffu, m[v], o);
    }
    int lane = threadIdx.x & 31, warp = threadIdx.x >> 5;
    if (lane == 0) {
#pragma unroll
        for (int v = 0; v < 54; v++) sred[warp][v] = m[v];
    }
    __syncthreads();
    if (threadIdx.x < 54) {
        float acc = 0.0f;
#pragma unroll
        for (int w = 0; w < 8; w++) acc += sred[w][threadIdx.x];
        atomicAdd(&g_mom[threadIdx.x], acc);
    }
}

// ---------------- BN1 affine params from moments ----------------
__global__ void k_bn1(const float* __restrict__ gamma1, const float* __restrict__ beta1) {
    int f = threadIdx.x;
    if (f >= 64) return;
    float mcol[9];
#pragma unroll
    for (int t = 0; t < 9; t++) mcol[t] = g_M1[t * 64 + f];
    float mean = 0.0f;
#pragma unroll
    for (int t = 0; t < 9; t++) mean = fmaf(g_mom[t], mcol[t], mean);
    mean /= (float)NN;
    float e2 = 0.0f;
    int k = 9;
#pragma unroll
    for (int i = 0; i < 9; i++) {
#pragma unroll
        for (int j = i; j < 9; j++) {
            float term = g_mom[k++] * mcol[i] * mcol[j];
            e2 += (i == j) ? term : 2.0f * term;
        }
    }
    e2 /= (float)NN;
    float var = e2 - mean * mean;
    float a = rsqrtf(var + EPS) * gamma1[f];
    g_a1[f] = a;
    g_sh1[f] = beta1[f] - mean * a;
}

// -------- layer-1b: z1 = relu(affine(S@M1)) in fp16 ----------
__global__ __launch_bounds__(256) void k_layer1b() {
    __shared__ float sM1[9 * 64];
    for (int i = threadIdx.x; i < 9 * 64; i += 256) sM1[i] = g_M1[i];
    __syncthreads();

    int lane = threadIdx.x & 31;
    int warp = (blockIdx.x * blockDim.x + threadIdx.x) >> 5;
    int nwarps = (gridDim.x * blockDim.x) >> 5;

    float2 av = ((const float2*)g_a1)[lane];
    float2 shv = ((const float2*)g_sh1)[lane];

    for (int v = warp; v < NN; v += nwarps) {
        float y0 = 0.f, y1 = 0.f;
#pragma unroll
        for (int t = 0; t < 9; t++) {
            float sv = g_S[(size_t)v * 9 + t];
            y0 = fmaf(sv, sM1[t * 64 + 2 * lane], y0);
            y1 = fmaf(sv, sM1[t * 64 + 2 * lane + 1], y1);
        }
        float z0 = fmaxf(fmaf(y0, av.x, shv.x), 0.f);
        float z1 = fmaxf(fmaf(y1, av.y, shv.y), 0.f);
        ((half2*)g_z1)[(size_t)v * 32 + lane] = __floats2half2_rn(z0, z1);
    }
}

// ---------- layer-2 aggregation: CSR pull-gather, zero atomics ----------
// agg2[v] = (1/deg_v)*z1[v] + sum_{s in in(v)} dis[s]*dis[v]*z1[s]
__global__ __launch_bounds__(256) void k_gather() {
    int lane = threadIdx.x & 31;
    int sub = lane & 7;                  // 16B chunk of 128B fp16 row (8 feats)
    int grp = lane >> 3;                 // 4 nodes per warp
    int gw = (blockIdx.x * blockDim.x + threadIdx.x) >> 5;
    int nw = (gridDim.x * blockDim.x) >> 5;

    for (int v = gw * 4 + grp; v < NN; v += nw * 4) {
        float dv = g_dis[v];
        int off0 = g_off[v], off1 = g_off[v + 1];
        uint4 raw = ((const uint4*)(g_z1 + (size_t)v * 64))[sub];
        float id = dv * dv;
        float2 p0 = __half22float2(*(half2*)&raw.x);
        float2 p1 = __half22float2(*(half2*)&raw.y);
        float2 p2 = __half22float2(*(half2*)&raw.z);
        float2 p3 = __half22float2(*(half2*)&raw.w);
        float a0 = id * p0.x, a1 = id * p0.y, a2 = id * p1.x, a3 = id * p1.y;
        float a4 = id * p2.x, a5 = id * p2.y, a6 = id * p3.x, a7 = id * p3.y;
        for (int i = off0; i < off1; i++) {
            int s = g_srcs[i];                        // broadcast within group
            float norm = g_dis[s] * dv;
            uint4 r = ((const uint4*)(g_z1 + (size_t)s * 64))[sub];
            float2 q0 = __half22float2(*(half2*)&r.x);
            float2 q1 = __half22float2(*(half2*)&r.y);
            float2 q2 = __half22float2(*(half2*)&r.z);
            float2 q3 = __half22float2(*(half2*)&r.w);
            a0 = fmaf(norm, q0.x, a0); a1 = fmaf(norm, q0.y, a1);
            a2 = fmaf(norm, q1.x, a2); a3 = fmaf(norm, q1.y, a3);
            a4 = fmaf(norm, q2.x, a4); a5 = fmaf(norm, q2.y, a5);
            a6 = fmaf(norm, q3.x, a6); a7 = fmaf(norm, q3.y, a7);
        }
        float4* dst = (float4*)(g_agg2 + (size_t)v * 64 + sub * 8);
        dst[0] = make_float4(a0, a1, a2, a3);
        dst[1] = make_float4(a4, a5, a6, a7);
    }
}

// ---------- layer-2 GEMM + BN2 stats + fused graph pooling ----------
#define TN 128
#define NB2 512
__global__ __launch_bounds__(256, 2) void k_layer2pool(const int* __restrict__ batch,
                                                       const float* __restrict__ W2) {
    __shared__ float4 As4[TN * 16];
    __shared__ float4 Bs4[64 * 16];
    int tid = threadIdx.x;
    int tf = tid & 15;
    int tn = tid >> 4;

    for (int i = tid; i < 1024; i += 256) Bs4[i] = ((const float4*)W2)[i];

    float psum[4] = {0, 0, 0, 0};
    float pmx[4], pmn[4];
#pragma unroll
    for (int j = 0; j < 4; j++) { pmx[j] = -__int_as_float(0x7F800000); pmn[j] = __int_as_float(0x7F800000); }
    int gcur = -1;
    float ss[4] = {0, 0, 0, 0}, sq[4] = {0, 0, 0, 0};

    int tiles = (NN + TN - 1) / TN;
    int tpb = (tiles + NB2 - 1) / NB2;
    int t0 = blockIdx.x * tpb;
    int t1 = min(t0 + tpb, tiles);

    for (int t = t0; t < t1; t++) {
        int base = t * TN;
        __syncthreads();
#pragma unroll
        for (int kb = 0; kb < 8; kb++) {
            int nl = tn + 16 * kb;
            int v = base + nl;
            float4 val = {0.f, 0.f, 0.f, 0.f};
            if (v < NN) val = ((const float4*)g_agg2)[(size_t)v * 16 + tf];
            As4[nl * 16 + tf] = val;
        }
        __syncthreads();

        float4 acc[8];
#pragma unroll
        for (int i = 0; i < 8; i++) acc[i] = make_float4(0.f, 0.f, 0.f, 0.f);
#pragma unroll 4
        for (int kk = 0; kk < 16; kk++) {
            float4 b0 = Bs4[(4 * kk + 0) * 16 + tf];
            float4 b1 = Bs4[(4 * kk + 1) * 16 + tf];
            float4 b2 = Bs4[(4 * kk + 2) * 16 + tf];
            float4 b3 = Bs4[(4 * kk + 3) * 16 + tf];
#pragma unroll
            for (int i = 0; i < 8; i++) {
                float4 a = As4[(tn * 8 + i) * 16 + kk];
                acc[i].x = fmaf(a.x, b0.x, fmaf(a.y, b1.x, fmaf(a.z, b2.x, fmaf(a.w, b3.x, acc[i].x))));
                acc[i].y = fmaf(a.x, b0.y, fmaf(a.y, b1.y, fmaf(a.z, b2.y, fmaf(a.w, b3.y, acc[i].y))));
                acc[i].z = fmaf(a.x, b0.z, fmaf(a.y, b1.z, fmaf(a.z, b2.z, fmaf(a.w, b3.z, acc[i].z))));
                acc[i].w = fmaf(a.x, b0.w, fmaf(a.y, b1.w, fmaf(a.z, b2.w, fmaf(a.w, b3.w, acc[i].w))));
            }
        }

#pragma unroll
        for (int i = 0; i < 8; i++) {
            int v = base + tn * 8 + i;
            if (v >= NN) break;
            int g = batch[v];
            if (g != gcur) {
                if (gcur >= 0) {
                    int pb = gcur * 64 + tf * 4;
#pragma unroll
                    for (int j = 0; j < 4; j++) {
                        atomicAdd(&g_psum[pb + j], psum[j]);
                        atomicMaxFloat(&g_pmax[pb + j], pmx[j]);
                        atomicMinFloat(&g_pmin[pb + j], pmn[j]);
                    }
                }
                gcur = g;
#pragma unroll
                for (int j = 0; j < 4; j++) {
                    psum[j] = 0.f;
                    pmx[j] = -__int_as_float(0x7F800000);
                    pmn[j] = __int_as_float(0x7F800000);
                }
            }
            float y[4] = {acc[i].x, acc[i].y, acc[i].z, acc[i].w};
#pragma unroll
            for (int j = 0; j < 4; j++) {
                psum[j] += y[j];
                pmx[j] = fmaxf(pmx[j], y[j]);
                pmn[j] = fminf(pmn[j], y[j]);
                ss[j] += y[j];
                sq[j] = fmaf(y[j], y[j], sq[j]);
            }
        }
    }
    if (gcur >= 0) {
        int pb = gcur * 64 + tf * 4;
#pragma unroll
        for (int j = 0; j < 4; j++) {
            atomicAdd(&g_psum[pb + j], psum[j]);
            atomicMaxFloat(&g_pmax[pb + j], pmx[j]);
            atomicMinFloat(&g_pmin[pb + j], pmn[j]);
        }
    }
#pragma unroll
    for (int j = 0; j < 4; j++) {
        atomicAdd(&g_s2[tf * 4 + j], ss[j]);
        atomicAdd(&g_q2[tf * 4 + j], sq[j]);
    }
}

// ---------------- finalize ----------------
__global__ void k_final(const float* __restrict__ gamma2, const float* __restrict__ beta2,
                        float* __restrict__ out) {
    int f = threadIdx.x;
    if (f >= 64) return;
    float mu = g_s2[f] / (float)NN;
    float var = g_q2[f] / (float)NN - mu * mu;
    float a = rsqrtf(var + EPS) * gamma2[f];
    float sh = beta2[f] - mu * a;
    for (int g = 0; g < GG; g++) {
        float mx = __int_as_float(g_pmax[g * 64 + f]);
        float mn = __int_as_float(g_pmin[g * 64 + f]);
        float chosen = (a >= 0.f) ? mx : mn;
        out[g * 128 + f] = fmaf(chosen, a, sh);
        float c = fmaxf((float)g_cnt[g], 1.f);
        out[g * 128 + 64 + f] = fmaf(g_psum[g * 64 + f] / c, a, sh);
    }
}

// ---------------- launch ----------------
extern "C" void kernel_launch(void* const* d_in, const int* in_sizes, int n_in,
                              void* d_out, int out_size) {
    const int* node_type = (const int*)d_in[0];
    const int* num_inv   = (const int*)d_in[1];
    const int* edge      = (const int*)d_in[2];
    const int* batch     = (const int*)d_in[3];
    const float* emb_type = (const float*)d_in[4];
    const float* emb_inv  = (const float*)d_in[5];
    const float* W1       = (const float*)d_in[6];
    const float* W2       = (const float*)d_in[8];
    const float* gamma1   = (const float*)d_in[10];
    const float* beta1    = (const float*)d_in[11];
    const float* gamma2   = (const float*)d_in[12];
    const float* beta2    = (const float*)d_in[13];
    float* out = (float*)d_out;

    const int* esrc = edge;
    const int* edst = edge + EE;

    void* pDeg;
    cudaGetSymbolAddress(&pDeg, g_deg);
    cudaMemsetAsync(pDeg, 0, (size_t)NN * sizeof(int));

    k_small_init<<<(GG * 64 + 255) / 256, 256>>>();
    k_cnt<<<1, 64>>>(batch);
    k_prep<<<1, 576>>>(emb_type, emb_inv, W1);
    k_deg<<<(EE + 255) / 256, 256>>>(edst);
    k_scan1<<<NBS, SCAN_B>>>();
    k_scan2<<<1, 1024>>>();
    k_scan3<<<NBS, SCAN_B>>>();
    k_scatter<<<(EE + 255) / 256, 256>>>(esrc, edst);
    k_dis<<<(NN + 255) / 256, 256>>>(node_type, num_inv);
    k_edge1<<<(EE + 255) / 256, 256>>>(esrc, edst);
    k_stats<<<296, 256>>>();
    k_bn1<<<1, 64>>>(gamma1, beta1);
    k_layer1b<<<1184, 256>>>();
    k_gather<<<1184, 256>>>();
    k_layer2pool<<<NB2, 256>>>(batch, W2);
    k_final<<<1, 64>>>(gamma2, beta2, out);
}